// round 1
// baseline (speedup 1.0000x reference)
#include <cuda_runtime.h>
#include <mma.h>

using namespace nvcuda;

#define R_DIM 600
#define D_DIM 240
#define N_DIM 840
#define H_DIM 8
#define C_DIM 64
#define HC 512
#define E_DIM 20000
#define ME 20840            // E + N (self loops)
#define F_CNN 1242
#define NEG 0.2f

// ---------------- scratch (device globals; no allocation allowed) ----------
__device__ float g_h[N_DIM * C_DIM];
__device__ float g_xl[N_DIM * HC];
__device__ float g_xr[N_DIM * HC];
__device__ float g_logits[ME * H_DIM];
__device__ int   g_count[N_DIM];
__device__ int   g_cursor[N_DIM];
__device__ int   g_offset[N_DIM + 1];
__device__ int   g_csr[ME];
__device__ float g_res[N_DIM * HC];
__device__ float g_cat[N_DIM * F_CNN];
__device__ float g_feat[N_DIM * F_CNN];

// ---------------- init ------------------------------------------------------
__global__ void k_init() {
    int t = blockIdx.x * blockDim.x + threadIdx.x;
    if (t < N_DIM) { g_count[t] = 0; g_cursor[t] = 0; }
}

// ---------------- h = [met@W_rna ; dis@W_dis] --------------------------------
__global__ void k_h(const float* __restrict__ met, const float* __restrict__ dis,
                    const float* __restrict__ Wr,  const float* __restrict__ Wd) {
    int r = blockIdx.x;          // 0..839
    int c = threadIdx.x;         // 0..63
    float acc = 0.f;
    if (r < R_DIM) {
        const float* row = met + (size_t)r * R_DIM;
        #pragma unroll 4
        for (int k = 0; k < R_DIM; k++) acc += row[k] * Wr[k * C_DIM + c];
    } else {
        int rr = r - R_DIM;
        const float* row = dis + (size_t)rr * D_DIM;
        #pragma unroll 4
        for (int k = 0; k < D_DIM; k++) acc += row[k] * Wd[k * C_DIM + c];
    }
    g_h[r * C_DIM + c] = acc;
}

// ---------------- xl = h@W_l + b_l ; xr = h@W_r + b_r ------------------------
__global__ void k_xlr(const float* __restrict__ Wl, const float* __restrict__ bl,
                      const float* __restrict__ Wr, const float* __restrict__ br) {
    int idx = blockIdx.x * blockDim.x + threadIdx.x;
    if (idx >= N_DIM * HC) return;
    int n = idx / HC, j = idx % HC;
    const float* hrow = g_h + n * C_DIM;
    float a = 0.f, b = 0.f;
    #pragma unroll 8
    for (int k = 0; k < C_DIM; k++) {
        float hk = hrow[k];
        a += hk * Wl[k * HC + j];
        b += hk * Wr[k * HC + j];
    }
    g_xl[idx] = a + bl[j];
    g_xr[idx] = b + br[j];
}

// ---------------- CSR build (counting sort by dst) ---------------------------
__device__ __forceinline__ int edge_dst(const int* ei, int e) {
    return (e < E_DIM) ? ei[E_DIM + e] : (e - E_DIM);
}
__device__ __forceinline__ int edge_src(const int* ei, int e) {
    return (e < E_DIM) ? ei[e] : (e - E_DIM);
}

__global__ void k_count(const int* __restrict__ ei) {
    int e = blockIdx.x * blockDim.x + threadIdx.x;
    if (e < ME) atomicAdd(&g_count[edge_dst(ei, e)], 1);
}

__global__ void k_scan() {
    __shared__ int s[1024];
    int t = threadIdx.x;
    s[t] = (t < N_DIM) ? g_count[t] : 0;
    __syncthreads();
    for (int o = 1; o < 1024; o <<= 1) {
        int v = s[t];
        int add = (t >= o) ? s[t - o] : 0;
        __syncthreads();
        s[t] = v + add;
        __syncthreads();
    }
    if (t < N_DIM) g_offset[t + 1] = s[t];
    if (t == 0)    g_offset[0] = 0;
}

__global__ void k_scatter(const int* __restrict__ ei) {
    int e = blockIdx.x * blockDim.x + threadIdx.x;
    if (e >= ME) return;
    int d = edge_dst(ei, e);
    int pos = g_offset[d] + atomicAdd(&g_cursor[d], 1);
    g_csr[pos] = e;
}

// ---------------- edge logits: one warp per edge -----------------------------
__global__ void k_logits(const int* __restrict__ ei, const float* __restrict__ att) {
    int e = (blockIdx.x * blockDim.x + threadIdx.x) >> 5;
    if (e >= ME) return;
    int lane = threadIdx.x & 31;
    int src = edge_src(ei, e);
    int dst = edge_dst(ei, e);
    const float* pl = g_xl + src * HC;
    const float* pr = g_xr + dst * HC;
    #pragma unroll
    for (int h = 0; h < H_DIM; h++) {
        int c0 = h * C_DIM + lane;
        float v1 = pl[c0] + pr[c0];
        float v2 = pl[c0 + 32] + pr[c0 + 32];
        v1 = v1 > 0.f ? v1 : NEG * v1;
        v2 = v2 > 0.f ? v2 : NEG * v2;
        float t = v1 * att[h * C_DIM + lane] + v2 * att[h * C_DIM + lane + 32];
        #pragma unroll
        for (int o = 16; o > 0; o >>= 1) t += __shfl_xor_sync(0xffffffffu, t, o);
        if (lane == 0) g_logits[e * H_DIM + h] = t;
    }
}

// ---------------- node softmax + aggregate: one warp per (node, head) --------
__global__ void k_agg(const int* __restrict__ ei, const float* __restrict__ gb) {
    int n = blockIdx.x;
    int h = threadIdx.x >> 5;     // 8 warps per block
    int lane = threadIdx.x & 31;
    int beg = g_offset[n], end = g_offset[n + 1];

    float m = -1e30f;
    for (int i = beg + lane; i < end; i += 32)
        m = fmaxf(m, g_logits[g_csr[i] * H_DIM + h]);
    #pragma unroll
    for (int o = 16; o > 0; o >>= 1) m = fmaxf(m, __shfl_xor_sync(0xffffffffu, m, o));

    float s = 0.f;
    for (int i = beg + lane; i < end; i += 32)
        s += expf(g_logits[g_csr[i] * H_DIM + h] - m);
    #pragma unroll
    for (int o = 16; o > 0; o >>= 1) s += __shfl_xor_sync(0xffffffffu, s, o);

    float inv = 1.f / (s + 1e-16f);

    float a0 = 0.f, a1 = 0.f;
    for (int i = beg; i < end; i++) {
        int e = g_csr[i];
        float alpha = expf(g_logits[e * H_DIM + h] - m) * inv;
        int src = edge_src(ei, e);
        const float* px = g_xl + src * HC + h * C_DIM;
        a0 += alpha * px[lane];
        a1 += alpha * px[lane + 32];
    }
    g_res[n * HC + h * C_DIM + lane]      = a0 + gb[h * C_DIM + lane];
    g_res[n * HC + h * C_DIM + lane + 32] = a1 + gb[h * C_DIM + lane + 32];
}

// ---------------- conv branches -> cat (N, 1242) ------------------------------
__global__ void k_conv(const float* __restrict__ w1,  const float* __restrict__ b1,
                       const float* __restrict__ w4,  const float* __restrict__ b4,
                       const float* __restrict__ w16, const float* __restrict__ b16,
                       const float* __restrict__ w32, const float* __restrict__ b32) {
    __shared__ float sx[HC];
    __shared__ float sw[2544]; // 48 + 192 + 768 + 1536
    int n = blockIdx.x;
    int tid = threadIdx.x;     // 512 threads
    sx[tid] = g_res[n * HC + tid];
    if (tid < 48)   sw[tid] = w1[tid];
    if (tid < 192)  sw[48 + tid] = w4[tid];
    for (int i = tid; i < 768; i += 512)  sw[240 + i] = w16[i];
    for (int i = tid; i < 1536; i += 512) sw[1008 + i] = w32[i];
    __syncthreads();

    for (int o = tid; o < F_CNN; o += 512) {
        float acc; const float* w; int p, kw;
        if (o < 384)       { int q = o;        int oc = q >> 6;  p = q & 63;  kw = 1;  w = sw + oc * 8;          acc = b1[oc]; }
        else if (o < 750)  { int q = o - 384;  int oc = q / 61;  p = q % 61;  kw = 4;  w = sw + 48 + oc * 32;    acc = b4[oc]; }
        else if (o < 1044) { int q = o - 750;  int oc = q / 49;  p = q % 49;  kw = 16; w = sw + 240 + oc * 128;  acc = b16[oc]; }
        else               { int q = o - 1044; int oc = q / 33;  p = q % 33;  kw = 32; w = sw + 1008 + oc * 256; acc = b32[oc]; }
        for (int hh = 0; hh < H_DIM; hh++) {
            const float* xr = sx + hh * C_DIM + p;
            const float* wr = w + hh * kw;
            for (int kk = 0; kk < kw; kk++) acc += xr[kk] * wr[kk];
        }
        g_cat[n * F_CNN + o] = fmaxf(acc, 0.f);
    }
}

// ---------------- FC GEMM (tf32 wmma): feat = relu(cat @ Wfc + bfc) ----------
#define BM 64
#define BN 64
#define BK 32

__global__ void k_fc(const float* __restrict__ Wfc, const float* __restrict__ bfc) {
    __shared__ float As[BM][BK + 4];   // 64 x 36
    __shared__ float Bs[BK][BN + 4];   // 32 x 68
    __shared__ float Cs[BM][BN + 4];   // 64 x 68
    int tid = threadIdx.x;             // 256
    int warp = tid >> 5;
    int wm = warp >> 1;                // 0..3 (16-row strip)
    int wn = warp & 1;                 // 0..1 (32-col strip)
    int m0 = blockIdx.y * BM;
    int n0 = blockIdx.x * BN;

    wmma::fragment<wmma::accumulator, 16, 16, 8, float> acc0, acc1;
    wmma::fill_fragment(acc0, 0.f);
    wmma::fill_fragment(acc1, 0.f);

    for (int k0 = 0; k0 < F_CNN; k0 += BK) {
        for (int i = tid; i < BM * BK; i += 256) {
            int r = i / BK, c = i % BK;
            int gr = m0 + r, gc = k0 + c;
            As[r][c] = (gr < N_DIM && gc < F_CNN) ? g_cat[gr * F_CNN + gc] : 0.f;
        }
        for (int i = tid; i < BK * BN; i += 256) {
            int r = i / BN, c = i % BN;
            int gr = k0 + r, gc = n0 + c;
            Bs[r][c] = (gr < F_CNN && gc < F_CNN) ? Wfc[(size_t)gr * F_CNN + gc] : 0.f;
        }
        __syncthreads();
        #pragma unroll
        for (int kk = 0; kk < BK; kk += 8) {
            wmma::fragment<wmma::matrix_a, 16, 16, 8, wmma::precision::tf32, wmma::row_major> a;
            wmma::fragment<wmma::matrix_b, 16, 16, 8, wmma::precision::tf32, wmma::row_major> b0, b1;
            wmma::load_matrix_sync(a, &As[wm * 16][kk], BK + 4);
            #pragma unroll
            for (int t = 0; t < a.num_elements; t++) a.x[t] = wmma::__float_to_tf32(a.x[t]);
            wmma::load_matrix_sync(b0, &Bs[kk][wn * 32], BN + 4);
            #pragma unroll
            for (int t = 0; t < b0.num_elements; t++) b0.x[t] = wmma::__float_to_tf32(b0.x[t]);
            wmma::load_matrix_sync(b1, &Bs[kk][wn * 32 + 16], BN + 4);
            #pragma unroll
            for (int t = 0; t < b1.num_elements; t++) b1.x[t] = wmma::__float_to_tf32(b1.x[t]);
            wmma::mma_sync(acc0, a, b0, acc0);
            wmma::mma_sync(acc1, a, b1, acc1);
        }
        __syncthreads();
    }

    wmma::store_matrix_sync(&Cs[wm * 16][wn * 32],      acc0, BN + 4, wmma::mem_row_major);
    wmma::store_matrix_sync(&Cs[wm * 16][wn * 32 + 16], acc1, BN + 4, wmma::mem_row_major);
    __syncthreads();
    for (int i = tid; i < BM * BN; i += 256) {
        int r = i / BN, c = i % BN;
        int gr = m0 + r, gc = n0 + c;
        if (gr < N_DIM && gc < F_CNN) {
            float v = Cs[r][c] + bfc[gc];
            g_feat[gr * F_CNN + gc] = v > 0.f ? v : 0.f;
        }
    }
}

// ---------------- pairs: outer product write (HBM-bound) ---------------------
#define NF2 621   // 1242/2

__global__ void k_pairs(float* __restrict__ out) {
    __shared__ float2 srna[NF2];
    int i = blockIdx.x;                 // 0..599
    int tid = threadIdx.x;              // 640
    const float2* rrow = (const float2*)(g_feat + (size_t)i * F_CNN);
    if (tid < NF2) srna[tid] = rrow[tid];
    __syncthreads();
    if (tid >= NF2) return;
    float2 rv = srna[tid];
    int j0 = blockIdx.y * 48;
    #pragma unroll 2
    for (int j = j0; j < j0 + 48; j++) {
        const float2* drow = (const float2*)(g_feat + (size_t)(R_DIM + j) * F_CNN);
        float2 dv = drow[tid];
        float2 o; o.x = rv.x * dv.x; o.y = rv.y * dv.y;
        float2* orow = (float2*)(out + (size_t)(i * D_DIM + j) * F_CNN);
        orow[tid] = o;
    }
}

__global__ void k_labels(const float* __restrict__ rel, float* __restrict__ out, size_t off) {
    int t = blockIdx.x * blockDim.x + threadIdx.x;
    if (t < R_DIM * D_DIM) out[off + t] = rel[t];
}

// ---------------- launch ------------------------------------------------------
extern "C" void kernel_launch(void* const* d_in, const int* in_sizes, int n_in,
                              void* d_out, int out_size) {
    const int*   ei   = (const int*)d_in[0];
    const float* met  = (const float*)d_in[1];
    const float* dis  = (const float*)d_in[2];
    const float* rel  = (const float*)d_in[3];
    const float* Wr   = (const float*)d_in[4];
    const float* Wd   = (const float*)d_in[5];
    const float* Wl   = (const float*)d_in[6];
    const float* bl   = (const float*)d_in[7];
    const float* Wrt  = (const float*)d_in[8];
    const float* br   = (const float*)d_in[9];
    const float* att  = (const float*)d_in[10];
    const float* gb   = (const float*)d_in[11];
    const float* c1w  = (const float*)d_in[12];
    const float* c1b  = (const float*)d_in[13];
    const float* c4w  = (const float*)d_in[14];
    const float* c4b  = (const float*)d_in[15];
    const float* c16w = (const float*)d_in[16];
    const float* c16b = (const float*)d_in[17];
    const float* c32w = (const float*)d_in[18];
    const float* c32b = (const float*)d_in[19];
    const float* Wfc  = (const float*)d_in[20];
    const float* bfc  = (const float*)d_in[21];
    float* out = (float*)d_out;

    k_init<<<1, 1024>>>();
    k_h<<<N_DIM, C_DIM>>>(met, dis, Wr, Wd);
    k_xlr<<<(N_DIM * HC + 255) / 256, 256>>>(Wl, bl, Wrt, br);
    k_count<<<(ME + 255) / 256, 256>>>(ei);
    k_scan<<<1, 1024>>>();
    k_scatter<<<(ME + 255) / 256, 256>>>(ei);
    k_logits<<<(ME * 32 + 255) / 256, 256>>>(ei, att);
    k_agg<<<N_DIM, 256>>>(ei, gb);
    k_conv<<<N_DIM, 512>>>(c1w, c1b, c4w, c4b, c16w, c16b, c32w, c32b);
    k_fc<<<dim3((F_CNN + BN - 1) / BN, (N_DIM + BM - 1) / BM), 256>>>(Wfc, bfc);
    k_pairs<<<dim3(R_DIM, 5), 640>>>(out);
    size_t labels_off = (size_t)out_size - (size_t)R_DIM * D_DIM;
    k_labels<<<(R_DIM * D_DIM + 255) / 256, 256>>>(rel, out, labels_off);
}

// round 2
// speedup vs baseline: 1.4021x; 1.4021x over previous
#include <cuda_runtime.h>
#include <mma.h>

using namespace nvcuda;

#define R_DIM 600
#define D_DIM 240
#define N_DIM 840
#define H_DIM 8
#define C_DIM 64
#define HC 512
#define E_DIM 20000
#define ME 20840            // E + N (self loops)
#define F_CNN 1242
#define NEG 0.2f

// ---------------- scratch (device globals; no allocation allowed) ----------
__device__ float g_xl[N_DIM * HC];
__device__ float g_xr[N_DIM * HC];
__device__ float g_logits[ME * H_DIM];
__device__ int   g_offset[N_DIM + 1];
__device__ int   g_csr[ME];
__device__ float g_res[N_DIM * HC];
__device__ float g_cat[N_DIM * F_CNN];
__device__ float g_feat[N_DIM * F_CNN];

// ---------------- edge helpers ----------------------------------------------
__device__ __forceinline__ int edge_dst(const int* ei, int e) {
    return (e < E_DIM) ? ei[E_DIM + e] : (e - E_DIM);
}
__device__ __forceinline__ int edge_src(const int* ei, int e) {
    return (e < E_DIM) ? ei[e] : (e - E_DIM);
}

// ---------------- graph prep: count + scan + scatter, single block ----------
__global__ void k_prep(const int* __restrict__ ei) {
    __shared__ int scnt[N_DIM];
    __shared__ int soff[1024];
    int t = threadIdx.x;                       // 1024 threads
    if (t < N_DIM) scnt[t] = 0;
    __syncthreads();
    for (int e = t; e < ME; e += 1024) atomicAdd(&scnt[edge_dst(ei, e)], 1);
    __syncthreads();
    soff[t] = (t < N_DIM) ? scnt[t] : 0;
    __syncthreads();
    for (int o = 1; o < 1024; o <<= 1) {
        int v = soff[t];
        int a = (t >= o) ? soff[t - o] : 0;
        __syncthreads();
        soff[t] = v + a;
        __syncthreads();
    }
    if (t < N_DIM) g_offset[t + 1] = soff[t];
    if (t == 0)    g_offset[0] = 0;
    // reuse scnt as write cursor = exclusive prefix
    if (t < N_DIM) scnt[t] = (t == 0) ? 0 : soff[t - 1];
    __syncthreads();
    for (int e = t; e < ME; e += 1024) {
        int d = edge_dst(ei, e);
        int pos = atomicAdd(&scnt[d], 1);
        g_csr[pos] = e;
    }
}

// ---------------- fused: h = feat@W, then xl/xr = h@W_l/W_r (8 nodes/block) --
__global__ void k_hx(const float* __restrict__ met, const float* __restrict__ dis,
                     const float* __restrict__ Wrna, const float* __restrict__ Wdis,
                     const float* __restrict__ Wl, const float* __restrict__ bl,
                     const float* __restrict__ Wr, const float* __restrict__ br) {
    __shared__ float srows[8][600];
    __shared__ float sh[8][C_DIM];
    int b = blockIdx.x;                  // 0..104 ; blocks 0..74 rna, 75..104 dis
    int tid = threadIdx.x;               // 512
    bool rna = (b < 75);
    int r0 = rna ? b * 8 : R_DIM + (b - 75) * 8;     // global node base (local row base below)
    int K  = rna ? R_DIM : D_DIM;
    const float* src = rna ? met : dis;
    int lr0 = rna ? b * 8 : (b - 75) * 8;            // local row in met/dis

    for (int i = tid; i < 8 * K; i += 512) {
        int g = i / K, k = i % K;
        srows[g][k] = src[(size_t)(lr0 + g) * K + k];
    }
    __syncthreads();

    {   // phase 1: h rows
        int g = tid >> 6, c = tid & 63;
        const float* W = rna ? Wrna : Wdis;
        float acc = 0.f;
        #pragma unroll 4
        for (int k = 0; k < K; k++) acc += srows[g][k] * W[k * C_DIM + c];
        sh[g][c] = acc;
    }
    __syncthreads();

    {   // phase 2: xl/xr for 8 nodes, W values reused across nodes in regs
        int j = tid;
        float al[8] = {0,0,0,0,0,0,0,0};
        float ar[8] = {0,0,0,0,0,0,0,0};
        #pragma unroll 4
        for (int k = 0; k < C_DIM; k++) {
            float wl = Wl[k * HC + j];
            float wr = Wr[k * HC + j];
            #pragma unroll
            for (int g = 0; g < 8; g++) {
                float hv = sh[g][k];
                al[g] += hv * wl;
                ar[g] += hv * wr;
            }
        }
        float bjl = bl[j], bjr = br[j];
        #pragma unroll
        for (int g = 0; g < 8; g++) {
            g_xl[(size_t)(r0 + g) * HC + j] = al[g] + bjl;
            g_xr[(size_t)(r0 + g) * HC + j] = ar[g] + bjr;
        }
    }
}

// ---------------- edge logits: one warp per edge -----------------------------
__global__ void k_logits(const int* __restrict__ ei, const float* __restrict__ att) {
    int e = (blockIdx.x * blockDim.x + threadIdx.x) >> 5;
    if (e >= ME) return;
    int lane = threadIdx.x & 31;
    int src = edge_src(ei, e);
    int dst = edge_dst(ei, e);
    const float* pl = g_xl + (size_t)src * HC;
    const float* pr = g_xr + (size_t)dst * HC;
    #pragma unroll
    for (int h = 0; h < H_DIM; h++) {
        int c0 = h * C_DIM + lane;
        float v1 = pl[c0] + pr[c0];
        float v2 = pl[c0 + 32] + pr[c0 + 32];
        v1 = v1 > 0.f ? v1 : NEG * v1;
        v2 = v2 > 0.f ? v2 : NEG * v2;
        float t = v1 * att[h * C_DIM + lane] + v2 * att[h * C_DIM + lane + 32];
        #pragma unroll
        for (int o = 16; o > 0; o >>= 1) t += __shfl_xor_sync(0xffffffffu, t, o);
        if (lane == 0) g_logits[e * H_DIM + h] = t;
    }
}

// ---------------- node softmax + aggregate: one warp per (node, head) --------
__global__ void k_agg(const int* __restrict__ ei, const float* __restrict__ gb) {
    int n = blockIdx.x;
    int h = threadIdx.x >> 5;     // 8 warps per block
    int lane = threadIdx.x & 31;
    int beg = g_offset[n], end = g_offset[n + 1];

    float m = -1e30f;
    for (int i = beg + lane; i < end; i += 32)
        m = fmaxf(m, g_logits[g_csr[i] * H_DIM + h]);
    #pragma unroll
    for (int o = 16; o > 0; o >>= 1) m = fmaxf(m, __shfl_xor_sync(0xffffffffu, m, o));

    float s = 0.f;
    for (int i = beg + lane; i < end; i += 32)
        s += expf(g_logits[g_csr[i] * H_DIM + h] - m);
    #pragma unroll
    for (int o = 16; o > 0; o >>= 1) s += __shfl_xor_sync(0xffffffffu, s, o);

    float inv = 1.f / (s + 1e-16f);

    float a0 = 0.f, a1 = 0.f;
    for (int i = beg; i < end; i++) {
        int e = g_csr[i];
        float alpha = expf(g_logits[e * H_DIM + h] - m) * inv;
        int src = edge_src(ei, e);
        const float* px = g_xl + (size_t)src * HC + h * C_DIM;
        a0 += alpha * px[lane];
        a1 += alpha * px[lane + 32];
    }
    g_res[n * HC + h * C_DIM + lane]      = a0 + gb[h * C_DIM + lane];
    g_res[n * HC + h * C_DIM + lane + 32] = a1 + gb[h * C_DIM + lane + 32];
}

// ---------------- conv branches (compile-time kw, fully unrolled) ------------
template<int KW>
__device__ __forceinline__ float conv_dot(const float* __restrict__ sx, int p,
                                          const float* __restrict__ w) {
    float acc = 0.f;
    #pragma unroll
    for (int h = 0; h < H_DIM; h++) {
        #pragma unroll
        for (int k = 0; k < KW; k++)
            acc += sx[h * C_DIM + p + k] * w[h * KW + k];
    }
    return acc;
}

__global__ void k_conv(const float* __restrict__ w1,  const float* __restrict__ b1,
                       const float* __restrict__ w4,  const float* __restrict__ b4,
                       const float* __restrict__ w16, const float* __restrict__ b16,
                       const float* __restrict__ w32, const float* __restrict__ b32) {
    __shared__ float sx[HC];
    __shared__ float sw[2544]; // 48 + 192 + 768 + 1536
    int n = blockIdx.x;
    int tid = threadIdx.x;     // 512 threads
    sx[tid] = g_res[n * HC + tid];
    if (tid < 48)   sw[tid] = w1[tid];
    if (tid < 192)  sw[48 + tid] = w4[tid];
    for (int i = tid; i < 768; i += 512)  sw[240 + i] = w16[i];
    for (int i = tid; i < 1536; i += 512) sw[1008 + i] = w32[i];
    __syncthreads();

    float* crow = g_cat + (size_t)n * F_CNN;
    if (tid < 384) {   // branch kw=1: 6 oc x 64 p
        int oc = tid >> 6, p = tid & 63;
        float v = b1[oc] + conv_dot<1>(sx, p, sw + oc * 8);
        crow[tid] = fmaxf(v, 0.f);
    }
    if (tid < 366) {   // branch kw=4: 6 x 61
        int oc = tid / 61, p = tid % 61;
        float v = b4[oc] + conv_dot<4>(sx, p, sw + 48 + oc * 32);
        crow[384 + tid] = fmaxf(v, 0.f);
    }
    if (tid < 294) {   // branch kw=16: 6 x 49
        int oc = tid / 49, p = tid % 49;
        float v = b16[oc] + conv_dot<16>(sx, p, sw + 240 + oc * 128);
        crow[750 + tid] = fmaxf(v, 0.f);
    }
    if (tid < 198) {   // branch kw=32: 6 x 33
        int oc = tid / 33, p = tid % 33;
        float v = b32[oc] + conv_dot<32>(sx, p, sw + 1008 + oc * 256);
        crow[1044 + tid] = fmaxf(v, 0.f);
    }
}

// ---------------- FC GEMM (tf32 wmma): feat = relu(cat @ Wfc + bfc) ----------
#define BM 64
#define BN 128
#define BK 32
#define LDA 36
#define LDB 132

__global__ void k_fc(const float* __restrict__ Wfc, const float* __restrict__ bfc) {
    __shared__ __align__(16) float buf[BM * LDB];  // 64*132 = 8448 floats (33.8KB)
    float* As = buf;                                // 64 x 36 = 2304
    float* Bs = buf + BM * LDA;                     // 32 x 132 = 4224
    float* Cs = buf;                                // epilogue alias

    int tid = threadIdx.x;             // 256
    int warp = tid >> 5;
    int wm = warp >> 1;                // 0..3  -> 16-row strip
    int wn = warp & 1;                 // 0..1  -> 64-col strip
    int m0 = blockIdx.y * BM;
    int n0 = blockIdx.x * BN;

    wmma::fragment<wmma::accumulator, 16, 16, 8, float> acc[4];
    #pragma unroll
    for (int t = 0; t < 4; t++) wmma::fill_fragment(acc[t], 0.f);

    for (int k0 = 0; k0 < F_CNN; k0 += BK) {
        #pragma unroll
        for (int t = 0; t < 8; t++) {            // 64*32/256 = 8 per thread
            int i = tid + t * 256;
            int r = i >> 5, c = i & 31;
            int gr = m0 + r, gc = k0 + c;
            float v = (gr < N_DIM && gc < F_CNN) ? g_cat[(size_t)gr * F_CNN + gc] : 0.f;
            As[r * LDA + c] = wmma::__float_to_tf32(v);
        }
        #pragma unroll
        for (int t = 0; t < 16; t++) {           // 32*128/256 = 16 per thread
            int i = tid + t * 256;
            int r = i >> 7, c = i & 127;
            int gr = k0 + r, gc = n0 + c;
            float v = (gr < F_CNN && gc < F_CNN) ? Wfc[(size_t)gr * F_CNN + gc] : 0.f;
            Bs[r * LDB + c] = wmma::__float_to_tf32(v);
        }
        __syncthreads();
        #pragma unroll
        for (int kk = 0; kk < BK; kk += 8) {
            wmma::fragment<wmma::matrix_a, 16, 16, 8, wmma::precision::tf32, wmma::row_major> a;
            wmma::load_matrix_sync(a, As + (wm * 16) * LDA + kk, LDA);
            #pragma unroll
            for (int t = 0; t < 4; t++) {
                wmma::fragment<wmma::matrix_b, 16, 16, 8, wmma::precision::tf32, wmma::row_major> bfr;
                wmma::load_matrix_sync(bfr, Bs + kk * LDB + wn * 64 + t * 16, LDB);
                wmma::mma_sync(acc[t], a, bfr, acc[t]);
            }
        }
        __syncthreads();
    }

    #pragma unroll
    for (int t = 0; t < 4; t++)
        wmma::store_matrix_sync(Cs + (wm * 16) * LDB + wn * 64 + t * 16, acc[t], LDB,
                                wmma::mem_row_major);
    __syncthreads();
    #pragma unroll
    for (int t = 0; t < 32; t++) {               // 64*128/256 = 32 per thread
        int i = tid + t * 256;
        int r = i >> 7, c = i & 127;
        int gr = m0 + r, gc = n0 + c;
        if (gr < N_DIM && gc < F_CNN) {
            float v = Cs[r * LDB + c] + bfc[gc];
            g_feat[(size_t)gr * F_CNN + gc] = v > 0.f ? v : 0.f;
        }
    }
}

// ---------------- pairs: outer product write (HBM-bound) + labels ------------
#define NF2 621   // 1242/2

__global__ void k_pairs(float* __restrict__ out, const float* __restrict__ rel,
                        size_t labels_off) {
    __shared__ float2 srna[NF2];
    int i = blockIdx.x;                 // 0..599
    int tid = threadIdx.x;              // 640
    const float2* rrow = (const float2*)(g_feat + (size_t)i * F_CNN);
    if (tid < NF2) srna[tid] = rrow[tid];
    __syncthreads();

    if (blockIdx.y == 0 && tid >= NF2 && tid < NF2 + 16) {
        // labels: 240 per i, written by 16 spare threads (15 each)
        int l = tid - NF2;
        for (int j = l; j < D_DIM; j += 16)
            out[labels_off + (size_t)i * D_DIM + j] = rel[(size_t)i * D_DIM + j];
    }
    if (tid >= NF2) return;
    float2 rv = srna[tid];
    int j0 = blockIdx.y * 48;
    #pragma unroll 2
    for (int j = j0; j < j0 + 48; j++) {
        const float2* drow = (const float2*)(g_feat + (size_t)(R_DIM + j) * F_CNN);
        float2 dv = drow[tid];
        float2 o; o.x = rv.x * dv.x; o.y = rv.y * dv.y;
        __stcs((float2*)(out + (size_t)(i * D_DIM + j) * F_CNN) + tid, o);
    }
}

// ---------------- launch ------------------------------------------------------
extern "C" void kernel_launch(void* const* d_in, const int* in_sizes, int n_in,
                              void* d_out, int out_size) {
    const int*   ei   = (const int*)d_in[0];
    const float* met  = (const float*)d_in[1];
    const float* dis  = (const float*)d_in[2];
    const float* rel  = (const float*)d_in[3];
    const float* Wr   = (const float*)d_in[4];
    const float* Wd   = (const float*)d_in[5];
    const float* Wl   = (const float*)d_in[6];
    const float* bl   = (const float*)d_in[7];
    const float* Wrt  = (const float*)d_in[8];
    const float* br   = (const float*)d_in[9];
    const float* att  = (const float*)d_in[10];
    const float* gb   = (const float*)d_in[11];
    const float* c1w  = (const float*)d_in[12];
    const float* c1b  = (const float*)d_in[13];
    const float* c4w  = (const float*)d_in[14];
    const float* c4b  = (const float*)d_in[15];
    const float* c16w = (const float*)d_in[16];
    const float* c16b = (const float*)d_in[17];
    const float* c32w = (const float*)d_in[18];
    const float* c32b = (const float*)d_in[19];
    const float* Wfc  = (const float*)d_in[20];
    const float* bfc  = (const float*)d_in[21];
    float* out = (float*)d_out;

    k_prep<<<1, 1024>>>(ei);
    k_hx<<<105, 512>>>(met, dis, Wr, Wd, Wl, bl, Wrt, br);
    k_logits<<<(ME * 32 + 255) / 256, 256>>>(ei, att);
    k_agg<<<N_DIM, 256>>>(ei, gb);
    k_conv<<<N_DIM, 512>>>(c1w, c1b, c4w, c4b, c16w, c16b, c32w, c32b);
    k_fc<<<dim3((F_CNN + BN - 1) / BN, (N_DIM + BM - 1) / BM), 256>>>(Wfc, bfc);
    size_t labels_off = (size_t)out_size - (size_t)R_DIM * D_DIM;
    k_pairs<<<dim3(R_DIM, 5), 640>>>(out, rel, labels_off);
}

// round 4
// speedup vs baseline: 1.4989x; 1.0691x over previous
#include <cuda_runtime.h>
#include <cstdint>
#include <mma.h>

using namespace nvcuda;

#define R_DIM 600
#define D_DIM 240
#define N_DIM 840
#define H_DIM 8
#define C_DIM 64
#define HC 512
#define E_DIM 20000
#define ME 20840            // E + N (self loops)
#define F_CNN 1242
#define NEG 0.2f

// padded dims for guard-free FC pipeline
#define KP 1248             // 39 * 32
#define NP 1280             // 20 * 64
#define MP 896              // 14 * 64

// ---------------- scratch (device globals; no allocation allowed) ----------
__device__ float g_xl[N_DIM * HC];
__device__ float g_xr[N_DIM * HC];
__device__ float g_logits[ME * H_DIM];
__device__ int   g_offset[N_DIM + 1];
__device__ int   g_csr[ME];
__device__ float g_cat[MP * NP];       // padded: rows 840..895 zero, cols 1242..1279 zero
__device__ float g_wp[KP * NP];        // padded Wfc
__device__ float g_feat[N_DIM * F_CNN];

// ---------------- cp.async helpers -------------------------------------------
__device__ __forceinline__ void cp16(float* dst_smem, const float* src) {
    unsigned int d = (unsigned int)__cvta_generic_to_shared(dst_smem);
    asm volatile("cp.async.cg.shared.global [%0], [%1], 16;\n" :: "r"(d), "l"(src) : "memory");
}
__device__ __forceinline__ void cp_commit() {
    asm volatile("cp.async.commit_group;\n" ::: "memory");
}
template<int W> __device__ __forceinline__ void cp_wait() {
    asm volatile("cp.async.wait_group %0;\n" :: "n"(W) : "memory");
}

// ---------------- edge helpers ------------------------------------------------
__device__ __forceinline__ int edge_dst(const int* ei, int e) {
    return (e < E_DIM) ? ei[E_DIM + e] : (e - E_DIM);
}
__device__ __forceinline__ int edge_src(const int* ei, int e) {
    return (e < E_DIM) ? ei[e] : (e - E_DIM);
}

// ---------------- pad kernel: Wfc -> g_wp, zero pad rows of g_cat ------------
__global__ void k_pad(const float* __restrict__ Wfc) {
    int idx = blockIdx.x * 256 + threadIdx.x;
    const int T1 = KP * NP;
    if (idx < T1) {
        int r = idx / NP, c = idx % NP;
        g_wp[idx] = (r < F_CNN && c < F_CNN) ? Wfc[(size_t)r * F_CNN + c] : 0.f;
    } else {
        int j = idx - T1;
        if (j < (MP - N_DIM) * NP)
            g_cat[(size_t)N_DIM * NP + j] = 0.f;
    }
}

// ---------------- graph prep: count + scan + scatter, single block ----------
__global__ void k_prep(const int* __restrict__ ei) {
    __shared__ int scnt[N_DIM];
    __shared__ int soff[1024];
    int t = threadIdx.x;                       // 1024 threads
    if (t < N_DIM) scnt[t] = 0;
    __syncthreads();
    for (int e = t; e < ME; e += 1024) atomicAdd(&scnt[edge_dst(ei, e)], 1);
    __syncthreads();
    soff[t] = (t < N_DIM) ? scnt[t] : 0;
    __syncthreads();
    for (int o = 1; o < 1024; o <<= 1) {
        int v = soff[t];
        int a = (t >= o) ? soff[t - o] : 0;
        __syncthreads();
        soff[t] = v + a;
        __syncthreads();
    }
    if (t < N_DIM) g_offset[t + 1] = soff[t];
    if (t == 0)    g_offset[0] = 0;
    if (t < N_DIM) scnt[t] = (t == 0) ? 0 : soff[t - 1];
    __syncthreads();
    for (int e = t; e < ME; e += 1024) {
        int d = edge_dst(ei, e);
        int pos = atomicAdd(&scnt[d], 1);
        g_csr[pos] = e;
    }
}

// ---------------- fused: h = feat@W, then xl/xr = h@W_l/W_r (8 nodes/block) --
__global__ void k_hx(const float* __restrict__ met, const float* __restrict__ dis,
                     const float* __restrict__ Wrna, const float* __restrict__ Wdis,
                     const float* __restrict__ Wl, const float* __restrict__ bl,
                     const float* __restrict__ Wr, const float* __restrict__ br) {
    __shared__ float srows[8][600];
    __shared__ float sh[8][C_DIM];
    int b = blockIdx.x;                  // 0..104 ; blocks 0..74 rna, 75..104 dis
    int tid = threadIdx.x;               // 512
    bool rna = (b < 75);
    int r0 = rna ? b * 8 : R_DIM + (b - 75) * 8;
    int K  = rna ? R_DIM : D_DIM;
    const float* src = rna ? met : dis;
    int lr0 = rna ? b * 8 : (b - 75) * 8;

    for (int i = tid; i < 8 * K; i += 512) {
        int g = i / K, k = i % K;
        srows[g][k] = src[(size_t)(lr0 + g) * K + k];
    }
    __syncthreads();

    {   // phase 1: h rows
        int g = tid >> 6, c = tid & 63;
        const float* W = rna ? Wrna : Wdis;
        float acc = 0.f;
        #pragma unroll 4
        for (int k = 0; k < K; k++) acc += srows[g][k] * W[k * C_DIM + c];
        sh[g][c] = acc;
    }
    __syncthreads();

    {   // phase 2: xl/xr for 8 nodes
        int j = tid;
        float al[8] = {0,0,0,0,0,0,0,0};
        float ar[8] = {0,0,0,0,0,0,0,0};
        #pragma unroll 4
        for (int k = 0; k < C_DIM; k++) {
            float wl = Wl[k * HC + j];
            float wr = Wr[k * HC + j];
            #pragma unroll
            for (int g = 0; g < 8; g++) {
                float hv = sh[g][k];
                al[g] += hv * wl;
                ar[g] += hv * wr;
            }
        }
        float bjl = bl[j], bjr = br[j];
        #pragma unroll
        for (int g = 0; g < 8; g++) {
            g_xl[(size_t)(r0 + g) * HC + j] = al[g] + bjl;
            g_xr[(size_t)(r0 + g) * HC + j] = ar[g] + bjr;
        }
    }
}

// ---------------- edge logits: one warp per edge, float4, all heads ----------
__global__ void k_logits(const int* __restrict__ ei, const float* __restrict__ att) {
    __shared__ float4 satt[128];
    int tid = threadIdx.x;                // 256
    if (tid < 128) satt[tid] = ((const float4*)att)[tid];
    __syncthreads();
    int e = (blockIdx.x * 256 + tid) >> 5;
    if (e >= ME) return;
    int lane = tid & 31;
    int src = edge_src(ei, e);
    int dst = edge_dst(ei, e);
    const float4* pl4 = (const float4*)(g_xl + (size_t)src * HC);
    const float4* pr4 = (const float4*)(g_xr + (size_t)dst * HC);
    int half = lane >> 4;
    #pragma unroll
    for (int q = 0; q < 4; q++) {
        int f = lane + 32 * q;
        float4 a = pl4[f];
        float4 b = pr4[f];
        float4 w = satt[f];
        float vx = a.x + b.x; vx = vx > 0.f ? vx : NEG * vx;
        float vy = a.y + b.y; vy = vy > 0.f ? vy : NEG * vy;
        float vz = a.z + b.z; vz = vz > 0.f ? vz : NEG * vz;
        float vw = a.w + b.w; vw = vw > 0.f ? vw : NEG * vw;
        float t = vx * w.x + vy * w.y + vz * w.z + vw * w.w;
        #pragma unroll
        for (int o = 8; o > 0; o >>= 1) t += __shfl_xor_sync(0xffffffffu, t, o);
        if ((lane & 15) == 0) g_logits[e * H_DIM + 2 * q + half] = t;
    }
}

// ---------------- conv dot (compile-time kw) ----------------------------------
template<int KW>
__device__ __forceinline__ float conv_dot(const float* __restrict__ sx, int p,
                                          const float* __restrict__ w) {
    float acc = 0.f;
    #pragma unroll
    for (int h = 0; h < H_DIM; h++) {
        #pragma unroll
        for (int k = 0; k < KW; k++)
            acc += sx[h * C_DIM + p + k] * w[h * KW + k];
    }
    return acc;
}

// ---------------- fused GAT aggregate + CNN branches --------------------------
__global__ void k_gatconv(const int* __restrict__ ei, const float* __restrict__ gb,
                          const float* __restrict__ w1,  const float* __restrict__ b1,
                          const float* __restrict__ w4,  const float* __restrict__ b4,
                          const float* __restrict__ w16, const float* __restrict__ b16,
                          const float* __restrict__ w32, const float* __restrict__ b32) {
    __shared__ float swt[2544];
    __shared__ float sbias[24];
    __shared__ float sm[H_DIM], sinv[H_DIM];
    __shared__ int   sedge[64], ssrc[64];
    __shared__ float salpha[8 * 64];
    __shared__ float sres[HC];
    int n = blockIdx.x;
    int tid = threadIdx.x;               // 256
    int h = tid >> 5, lane = tid & 31;

    for (int i = tid; i < 2544; i += 256)
        swt[i] = (i < 48) ? w1[i] : (i < 240) ? w4[i - 48]
               : (i < 1008) ? w16[i - 240] : w32[i - 1008];
    if (tid < 24)
        sbias[tid] = (tid < 6) ? b1[tid] : (tid < 12) ? b4[tid - 6]
                   : (tid < 18) ? b16[tid - 12] : b32[tid - 18];

    int beg = g_offset[n], end = g_offset[n + 1], deg = end - beg;

    // phase A: per-head max and sum (warp h)
    float m = -1e30f;
    for (int i = beg + lane; i < end; i += 32)
        m = fmaxf(m, g_logits[g_csr[i] * H_DIM + h]);
    #pragma unroll
    for (int o = 16; o > 0; o >>= 1) m = fmaxf(m, __shfl_xor_sync(0xffffffffu, m, o));
    float s = 0.f;
    for (int i = beg + lane; i < end; i += 32)
        s += expf(g_logits[g_csr[i] * H_DIM + h] - m);
    #pragma unroll
    for (int o = 16; o > 0; o >>= 1) s += __shfl_xor_sync(0xffffffffu, s, o);
    if (lane == 0) { sm[h] = m; sinv[h] = 1.f / (s + 1e-16f); }
    __syncthreads();

    // phase B: aggregate, thread t owns channels t and t+256
    float acc0 = gb[tid], acc1 = gb[tid + 256];
    int h0 = tid >> 6, h1 = (tid + 256) >> 6;
    for (int c0 = 0; c0 < deg; c0 += 64) {
        int nch = min(64, deg - c0);
        if (tid < nch) {
            int e = g_csr[beg + c0 + tid];
            sedge[tid] = e;
            ssrc[tid] = edge_src(ei, e);
        }
        __syncthreads();
        {
            int i = tid & 63, hh = tid >> 6;
            if (i < nch) salpha[hh * 64 + i] =
                expf(g_logits[sedge[i] * H_DIM + hh] - sm[hh]) * sinv[hh];
            i = (tid + 256) & 63; hh = (tid + 256) >> 6;
            if (i < nch) salpha[hh * 64 + i] =
                expf(g_logits[sedge[i] * H_DIM + hh] - sm[hh]) * sinv[hh];
        }
        __syncthreads();
        for (int i = 0; i < nch; i++) {
            const float* px = g_xl + (size_t)ssrc[i] * HC;
            acc0 += salpha[h0 * 64 + i] * px[tid];
            acc1 += salpha[h1 * 64 + i] * px[tid + 256];
        }
        __syncthreads();
    }
    sres[tid] = acc0;
    sres[tid + 256] = acc1;
    __syncthreads();

    // phase C: conv branches on smem row -> padded g_cat row
    float* crow = g_cat + (size_t)n * NP;
    for (int o = tid; o < NP; o += 256) {
        float v = 0.f;
        if (o < 384)       { int oc = o >> 6;          int p = o & 63;        v = sbias[oc]      + conv_dot<1>(sres, p, swt + oc * 8); }
        else if (o < 750)  { int q = o - 384;  int oc = q / 61; int p = q % 61; v = sbias[6 + oc]  + conv_dot<4>(sres, p, swt + 48 + oc * 32); }
        else if (o < 1044) { int q = o - 750;  int oc = q / 49; int p = q % 49; v = sbias[12 + oc] + conv_dot<16>(sres, p, swt + 240 + oc * 128); }
        else if (o < 1242) { int q = o - 1044; int oc = q / 33; int p = q % 33; v = sbias[18 + oc] + conv_dot<32>(sres, p, swt + 1008 + oc * 256); }
        crow[o] = fmaxf(v, 0.f);
    }
}

// ---------------- FC GEMM (tf32 wmma + cp.async double buffer) ---------------
#define BM 64
#define BN 64
#define BK 32
#define LDA 36
#define LDB 68
#define NT 39   // KP / BK
#define STG (BM * LDA + BK * LDB)   // 2304 + 2176 = 4480

__global__ void k_fc(const float* __restrict__ bfc) {
    __shared__ __align__(16) float buf[2][STG];
    int tid = threadIdx.x;             // 256
    int warp = tid >> 5;
    int wm = warp >> 1;                // 0..3 -> 16-row strip
    int wn = warp & 1;                 // 0..1 -> 32-col strip
    int m0 = blockIdx.y * BM;
    int n0 = blockIdx.x * BN;

    wmma::fragment<wmma::accumulator, 16, 16, 8, float> acc[2];
    wmma::fill_fragment(acc[0], 0.f);
    wmma::fill_fragment(acc[1], 0.f);

    auto load_stage = [&](int s, int kt) {
        float* As = buf[s];
        float* Bs = buf[s] + BM * LDA;
        int k0 = kt * BK;
        #pragma unroll
        for (int t = 0; t < 2; t++) {          // A: 512 float4
            int i = tid + t * 256;
            int r = i >> 3, c4 = i & 7;
            cp16(As + r * LDA + c4 * 4, g_cat + (size_t)(m0 + r) * NP + k0 + c4 * 4);
        }
        #pragma unroll
        for (int t = 0; t < 2; t++) {          // B: 512 float4
            int i = tid + t * 256;
            int r = i >> 4, c4 = i & 15;
            cp16(Bs + r * LDB + c4 * 4, g_wp + (size_t)(k0 + r) * NP + n0 + c4 * 4);
        }
        cp_commit();
    };

    load_stage(0, 0);
    for (int t = 0; t < NT; t++) {
        int s = t & 1;
        if (t + 1 < NT) { load_stage(s ^ 1, t + 1); cp_wait<1>(); }
        else            { cp_wait<0>(); }
        __syncthreads();
        const float* As = buf[s];
        const float* Bs = buf[s] + BM * LDA;
        #pragma unroll
        for (int kk = 0; kk < BK; kk += 8) {
            wmma::fragment<wmma::matrix_a, 16, 16, 8, wmma::precision::tf32, wmma::row_major> a;
            wmma::load_matrix_sync(a, As + (wm * 16) * LDA + kk, LDA);
            #pragma unroll
            for (int u = 0; u < a.num_elements; u++) a.x[u] = wmma::__float_to_tf32(a.x[u]);
            #pragma unroll
            for (int v = 0; v < 2; v++) {
                wmma::fragment<wmma::matrix_b, 16, 16, 8, wmma::precision::tf32, wmma::row_major> bf;
                wmma::load_matrix_sync(bf, Bs + kk * LDB + wn * 32 + v * 16, LDB);
                #pragma unroll
                for (int u = 0; u < bf.num_elements; u++) bf.x[u] = wmma::__float_to_tf32(bf.x[u]);
                wmma::mma_sync(acc[v], a, bf, acc[v]);
            }
        }
        __syncthreads();
    }

    float* Cs = buf[0];
    #pragma unroll
    for (int v = 0; v < 2; v++)
        wmma::store_matrix_sync(Cs + (wm * 16) * LDB + wn * 32 + v * 16, acc[v], LDB,
                                wmma::mem_row_major);
    __syncthreads();
    #pragma unroll
    for (int t = 0; t < 16; t++) {
        int i = tid + t * 256;
        int r = i >> 6, c = i & 63;
        int gr = m0 + r, gc = n0 + c;
        if (gr < N_DIM && gc < F_CNN) {
            float v = Cs[r * LDB + c] + bfc[gc];
            g_feat[(size_t)gr * F_CNN + gc] = v > 0.f ? v : 0.f;
        }
    }
}

// ---------------- pairs: outer product write (HBM-bound) + labels ------------
#define NF2 621   // 1242/2

__global__ void k_pairs(float* __restrict__ out, const float* __restrict__ rel,
                        size_t labels_off) {
    __shared__ float2 srna[NF2];
    int i = blockIdx.x;                 // 0..599
    int tid = threadIdx.x;              // 640
    const float2* rrow = (const float2*)(g_feat + (size_t)i * F_CNN);
    if (tid < NF2) srna[tid] = rrow[tid];
    __syncthreads();

    if (blockIdx.y == 0 && tid >= NF2 && tid < NF2 + 16) {
        int l = tid - NF2;
        for (int j = l; j < D_DIM; j += 16)
            out[labels_off + (size_t)i * D_DIM + j] = rel[(size_t)i * D_DIM + j];
    }
    if (tid >= NF2) return;
    float2 rv = srna[tid];
    int j0 = blockIdx.y * 48;
    #pragma unroll 2
    for (int j = j0; j < j0 + 48; j++) {
        const float2* drow = (const float2*)(g_feat + (size_t)(R_DIM + j) * F_CNN);
        float2 dv = drow[tid];
        float2 o; o.x = rv.x * dv.x; o.y = rv.y * dv.y;
        __stcs((float2*)(out + (size_t)(i * D_DIM + j) * F_CNN) + tid, o);
    }
}

// ---------------- launch ------------------------------------------------------
extern "C" void kernel_launch(void* const* d_in, const int* in_sizes, int n_in,
                              void* d_out, int out_size) {
    const int*   ei   = (const int*)d_in[0];
    const float* met  = (const float*)d_in[1];
    const float* dis  = (const float*)d_in[2];
    const float* rel  = (const float*)d_in[3];
    const float* Wr   = (const float*)d_in[4];
    const float* Wd   = (const float*)d_in[5];
    const float* Wl   = (const float*)d_in[6];
    const float* bl   = (const float*)d_in[7];
    const float* Wrt  = (const float*)d_in[8];
    const float* br   = (const float*)d_in[9];
    const float* att  = (const float*)d_in[10];
    const float* gb   = (const float*)d_in[11];
    const float* c1w  = (const float*)d_in[12];
    const float* c1b  = (const float*)d_in[13];
    const float* c4w  = (const float*)d_in[14];
    const float* c4b  = (const float*)d_in[15];
    const float* c16w = (const float*)d_in[16];
    const float* c16b = (const float*)d_in[17];
    const float* c32w = (const float*)d_in[18];
    const float* c32b = (const float*)d_in[19];
    const float* Wfc  = (const float*)d_in[20];
    const float* bfc  = (const float*)d_in[21];
    float* out = (float*)d_out;

    int pad_total = KP * NP + (MP - N_DIM) * NP;
    k_pad<<<(pad_total + 255) / 256, 256>>>(Wfc);
    k_prep<<<1, 1024>>>(ei);
    k_hx<<<105, 512>>>(met, dis, Wr, Wd, Wl, bl, Wrt, br);
    k_logits<<<(ME * 32 + 255) / 256, 256>>>(ei, att);
    k_gatconv<<<N_DIM, 256>>>(ei, gb, c1w, c1b, c4w, c4b, c16w, c16b, c32w, c32b);
    k_fc<<<dim3(NP / BN, MP / BM), 256>>>(bfc);
    size_t labels_off = (size_t)out_size - (size_t)R_DIM * D_DIM;
    k_pairs<<<dim3(R_DIM, 5), 640>>>(out, rel, labels_off);
}

// round 5
// speedup vs baseline: 1.5507x; 1.0346x over previous
#include <cuda_runtime.h>
#include <cstdint>
#include <mma.h>

using namespace nvcuda;

#define R_DIM 600
#define D_DIM 240
#define N_DIM 840
#define H_DIM 8
#define C_DIM 64
#define HC 512
#define E_DIM 20000
#define ME 20840            // E + N (self loops)
#define F_CNN 1242
#define NEG 0.2f

// padded dims for guard-free FC pipeline
#define KP 1248             // 39 * 32
#define NP 1280             // 20 * 64
#define MP 896              // 7 * 128

// ---------------- scratch (device globals; no allocation allowed) ----------
__device__ float g_xl[N_DIM * HC];
__device__ float g_xr[N_DIM * HC];
__device__ float g_logits[ME * H_DIM];
__device__ int   g_offset[N_DIM + 1];
__device__ int   g_csr[ME];
__device__ float g_cat[MP * NP];       // padded, tf32-rounded
__device__ float g_wp[KP * NP];        // padded Wfc, tf32-rounded
__device__ float g_feat[N_DIM * F_CNN];

// ---------------- cp.async helpers -------------------------------------------
__device__ __forceinline__ void cp16(float* dst_smem, const float* src) {
    unsigned int d = (unsigned int)__cvta_generic_to_shared(dst_smem);
    asm volatile("cp.async.cg.shared.global [%0], [%1], 16;\n" :: "r"(d), "l"(src) : "memory");
}
__device__ __forceinline__ void cp_commit() {
    asm volatile("cp.async.commit_group;\n" ::: "memory");
}
template<int W> __device__ __forceinline__ void cp_wait() {
    asm volatile("cp.async.wait_group %0;\n" :: "n"(W) : "memory");
}

// ---------------- edge helpers ------------------------------------------------
__device__ __forceinline__ int edge_dst(const int* ei, int e) {
    return (e < E_DIM) ? ei[E_DIM + e] : (e - E_DIM);
}
__device__ __forceinline__ int edge_src(const int* ei, int e) {
    return (e < E_DIM) ? ei[e] : (e - E_DIM);
}

// ---------------- pad kernel: Wfc -> g_wp (tf32), zero-pad g_cat rows --------
__global__ void k_pad(const float* __restrict__ Wfc) {
    int idx = blockIdx.x * 256 + threadIdx.x;
    const int T1 = KP * NP;
    if (idx < T1) {
        int r = idx / NP, c = idx % NP;
        float v = (r < F_CNN && c < F_CNN) ? Wfc[(size_t)r * F_CNN + c] : 0.f;
        g_wp[idx] = wmma::__float_to_tf32(v);
    } else {
        int j = idx - T1;
        if (j < (MP - N_DIM) * NP)
            g_cat[(size_t)N_DIM * NP + j] = 0.f;
    }
}

// ---------------- graph prep: count + scan + scatter, single block ----------
__global__ void k_prep(const int* __restrict__ ei) {
    __shared__ int scnt[N_DIM];
    __shared__ int soff[1024];
    int t = threadIdx.x;                       // 1024 threads
    if (t < N_DIM) scnt[t] = 0;
    __syncthreads();
    for (int e = t; e < ME; e += 1024) atomicAdd(&scnt[edge_dst(ei, e)], 1);
    __syncthreads();
    soff[t] = (t < N_DIM) ? scnt[t] : 0;
    __syncthreads();
    for (int o = 1; o < 1024; o <<= 1) {
        int v = soff[t];
        int a = (t >= o) ? soff[t - o] : 0;
        __syncthreads();
        soff[t] = v + a;
        __syncthreads();
    }
    if (t < N_DIM) g_offset[t + 1] = soff[t];
    if (t == 0)    g_offset[0] = 0;
    if (t < N_DIM) scnt[t] = (t == 0) ? 0 : soff[t - 1];
    __syncthreads();
    for (int e = t; e < ME; e += 1024) {
        int d = edge_dst(ei, e);
        int pos = atomicAdd(&scnt[d], 1);
        g_csr[pos] = e;
    }
}

// ---------------- fused: h = feat@W, then xl/xr = h@W_l/W_r (8 nodes/block) --
__global__ void k_hx(const float* __restrict__ met, const float* __restrict__ dis,
                     const float* __restrict__ Wrna, const float* __restrict__ Wdis,
                     const float* __restrict__ Wl, const float* __restrict__ bl,
                     const float* __restrict__ Wr, const float* __restrict__ br) {
    __shared__ float srows[8][600];
    __shared__ float sh[8][C_DIM];
    int b = blockIdx.x;                  // 0..104 ; blocks 0..74 rna, 75..104 dis
    int tid = threadIdx.x;               // 512
    bool rna = (b < 75);
    int r0 = rna ? b * 8 : R_DIM + (b - 75) * 8;
    int K  = rna ? R_DIM : D_DIM;
    const float* src = rna ? met : dis;
    int lr0 = rna ? b * 8 : (b - 75) * 8;

    for (int i = tid; i < 8 * K; i += 512) {
        int g = i / K, k = i % K;
        srows[g][k] = src[(size_t)(lr0 + g) * K + k];
    }
    __syncthreads();

    {   // phase 1: h rows
        int g = tid >> 6, c = tid & 63;
        const float* W = rna ? Wrna : Wdis;
        float acc = 0.f;
        #pragma unroll 4
        for (int k = 0; k < K; k++) acc += srows[g][k] * W[k * C_DIM + c];
        sh[g][c] = acc;
    }
    __syncthreads();

    {   // phase 2: xl/xr for 8 nodes
        int j = tid;
        float al[8] = {0,0,0,0,0,0,0,0};
        float ar[8] = {0,0,0,0,0,0,0,0};
        #pragma unroll 4
        for (int k = 0; k < C_DIM; k++) {
            float wl = Wl[k * HC + j];
            float wr = Wr[k * HC + j];
            #pragma unroll
            for (int g = 0; g < 8; g++) {
                float hv = sh[g][k];
                al[g] += hv * wl;
                ar[g] += hv * wr;
            }
        }
        float bjl = bl[j], bjr = br[j];
        #pragma unroll
        for (int g = 0; g < 8; g++) {
            g_xl[(size_t)(r0 + g) * HC + j] = al[g] + bjl;
            g_xr[(size_t)(r0 + g) * HC + j] = ar[g] + bjr;
        }
    }
}

// ---------------- edge logits: one warp per edge, batched float4 loads -------
__global__ void k_logits(const int* __restrict__ ei, const float* __restrict__ att) {
    __shared__ float4 satt[128];
    int tid = threadIdx.x;                // 256
    if (tid < 128) satt[tid] = ((const float4*)att)[tid];
    __syncthreads();
    int e = (blockIdx.x * 256 + tid) >> 5;
    if (e >= ME) return;
    int lane = tid & 31;
    int src = edge_src(ei, e);
    int dst = edge_dst(ei, e);
    const float4* pl4 = (const float4*)(g_xl + (size_t)src * HC);
    const float4* pr4 = (const float4*)(g_xr + (size_t)dst * HC);

    // batch all 8 loads up front (MLP)
    float4 a[4], b[4];
    #pragma unroll
    for (int q = 0; q < 4; q++) { a[q] = pl4[lane + 32 * q]; b[q] = pr4[lane + 32 * q]; }

    int half = lane >> 4;
    #pragma unroll
    for (int q = 0; q < 4; q++) {
        float4 w = satt[lane + 32 * q];
        float vx = a[q].x + b[q].x; vx = vx > 0.f ? vx : NEG * vx;
        float vy = a[q].y + b[q].y; vy = vy > 0.f ? vy : NEG * vy;
        float vz = a[q].z + b[q].z; vz = vz > 0.f ? vz : NEG * vz;
        float vw = a[q].w + b[q].w; vw = vw > 0.f ? vw : NEG * vw;
        float t = vx * w.x + vy * w.y + vz * w.z + vw * w.w;
        #pragma unroll
        for (int o = 8; o > 0; o >>= 1) t += __shfl_xor_sync(0xffffffffu, t, o);
        if ((lane & 15) == 0) g_logits[e * H_DIM + 2 * q + half] = t;
    }
}

// ---------------- conv dot (compile-time kw) ----------------------------------
template<int KW>
__device__ __forceinline__ float conv_dot(const float* __restrict__ sx, int p,
                                          const float* __restrict__ w) {
    float acc = 0.f;
    #pragma unroll
    for (int h = 0; h < H_DIM; h++) {
        #pragma unroll
        for (int k = 0; k < KW; k++)
            acc += sx[h * C_DIM + p + k] * w[h * KW + k];
    }
    return acc;
}

// ---------------- fused GAT aggregate + CNN branches --------------------------
__global__ void k_gatconv(const int* __restrict__ ei, const float* __restrict__ gb,
                          const float* __restrict__ w1,  const float* __restrict__ b1,
                          const float* __restrict__ w4,  const float* __restrict__ b4,
                          const float* __restrict__ w16, const float* __restrict__ b16,
                          const float* __restrict__ w32, const float* __restrict__ b32) {
    __shared__ float swt[2544];
    __shared__ float sbias[24];
    __shared__ float sm[H_DIM], sinv[H_DIM];
    __shared__ int   sedge[64], ssrc[64];
    __shared__ float salpha[8 * 64];
    __shared__ float sres[HC];
    int n = blockIdx.x;
    int tid = threadIdx.x;               // 256
    int h = tid >> 5, lane = tid & 31;

    for (int i = tid; i < 2544; i += 256)
        swt[i] = (i < 48) ? w1[i] : (i < 240) ? w4[i - 48]
               : (i < 1008) ? w16[i - 240] : w32[i - 1008];
    if (tid < 24)
        sbias[tid] = (tid < 6) ? b1[tid] : (tid < 12) ? b4[tid - 6]
                   : (tid < 18) ? b16[tid - 12] : b32[tid - 18];

    int beg = g_offset[n], end = g_offset[n + 1], deg = end - beg;

    // phase A: per-head max and sum (warp h)
    float m = -1e30f;
    for (int i = beg + lane; i < end; i += 32)
        m = fmaxf(m, g_logits[g_csr[i] * H_DIM + h]);
    #pragma unroll
    for (int o = 16; o > 0; o >>= 1) m = fmaxf(m, __shfl_xor_sync(0xffffffffu, m, o));
    float s = 0.f;
    for (int i = beg + lane; i < end; i += 32)
        s += __expf(g_logits[g_csr[i] * H_DIM + h] - m);
    #pragma unroll
    for (int o = 16; o > 0; o >>= 1) s += __shfl_xor_sync(0xffffffffu, s, o);
    if (lane == 0) { sm[h] = m; sinv[h] = 1.f / (s + 1e-16f); }
    __syncthreads();

    // phase B: aggregate, thread t owns channels t and t+256
    float acc0 = gb[tid], acc1 = gb[tid + 256];
    int h0 = tid >> 6, h1 = (tid + 256) >> 6;
    for (int c0 = 0; c0 < deg; c0 += 64) {
        int nch = min(64, deg - c0);
        if (tid < nch) {
            int e = g_csr[beg + c0 + tid];
            sedge[tid] = e;
            ssrc[tid] = edge_src(ei, e);
        }
        __syncthreads();
        {
            int i = tid & 63, hh = tid >> 6;
            if (i < nch) salpha[hh * 64 + i] =
                __expf(g_logits[sedge[i] * H_DIM + hh] - sm[hh]) * sinv[hh];
            i = (tid + 256) & 63; hh = (tid + 256) >> 6;
            if (i < nch) salpha[hh * 64 + i] =
                __expf(g_logits[sedge[i] * H_DIM + hh] - sm[hh]) * sinv[hh];
        }
        __syncthreads();
        for (int i = 0; i < nch; i++) {
            const float* px = g_xl + (size_t)ssrc[i] * HC;
            acc0 += salpha[h0 * 64 + i] * px[tid];
            acc1 += salpha[h1 * 64 + i] * px[tid + 256];
        }
        __syncthreads();
    }
    sres[tid] = acc0;
    sres[tid + 256] = acc1;
    __syncthreads();

    // phase C: conv branches on smem row -> padded g_cat row (tf32-rounded)
    float* crow = g_cat + (size_t)n * NP;
    for (int o = tid; o < NP; o += 256) {
        float v = 0.f;
        if (o < 384)       { int oc = o >> 6;          int p = o & 63;        v = sbias[oc]      + conv_dot<1>(sres, p, swt + oc * 8); }
        else if (o < 750)  { int q = o - 384;  int oc = q / 61; int p = q % 61; v = sbias[6 + oc]  + conv_dot<4>(sres, p, swt + 48 + oc * 32); }
        else if (o < 1044) { int q = o - 750;  int oc = q / 49; int p = q % 49; v = sbias[12 + oc] + conv_dot<16>(sres, p, swt + 240 + oc * 128); }
        else if (o < 1242) { int q = o - 1044; int oc = q / 33; int p = q % 33; v = sbias[18 + oc] + conv_dot<32>(sres, p, swt + 1008 + oc * 256); }
        crow[o] = wmma::__float_to_tf32(fmaxf(v, 0.f));
    }
}

// ---------------- FC GEMM (tf32 wmma + cp.async double buffer) ---------------
#define BM 128
#define BN 64
#define BK 32
#define LDA 36
#define LDB 68
#define NT 39   // KP / BK
#define STG (BM * LDA + BK * LDB)   // 4608 + 2176 = 6784 floats
#define FC_SMEM (2 * STG * 4)       // 54272 bytes

extern __shared__ float fcbuf[];

__global__ void k_fc(const float* __restrict__ bfc) {
    int tid = threadIdx.x;             // 256
    int warp = tid >> 5;
    int wm = warp >> 1;                // 0..3 -> 32-row strip
    int wn = warp & 1;                 // 0..1 -> 32-col strip
    int m0 = blockIdx.y * BM;
    int n0 = blockIdx.x * BN;

    wmma::fragment<wmma::accumulator, 16, 16, 8, float> acc[2][2];
    #pragma unroll
    for (int i = 0; i < 2; i++)
        #pragma unroll
        for (int j = 0; j < 2; j++) wmma::fill_fragment(acc[i][j], 0.f);

    auto load_stage = [&](int s, int kt) {
        float* As = fcbuf + s * STG;
        float* Bs = As + BM * LDA;
        int k0 = kt * BK;
        #pragma unroll
        for (int t = 0; t < 4; t++) {          // A: 1024 float4
            int i = tid + t * 256;
            int r = i >> 3, c4 = i & 7;
            cp16(As + r * LDA + c4 * 4, g_cat + (size_t)(m0 + r) * NP + k0 + c4 * 4);
        }
        #pragma unroll
        for (int t = 0; t < 2; t++) {          // B: 512 float4
            int i = tid + t * 256;
            int r = i >> 4, c4 = i & 15;
            cp16(Bs + r * LDB + c4 * 4, g_wp + (size_t)(k0 + r) * NP + n0 + c4 * 4);
        }
        cp_commit();
    };

    load_stage(0, 0);
    for (int t = 0; t < NT; t++) {
        int s = t & 1;
        if (t + 1 < NT) { load_stage(s ^ 1, t + 1); cp_wait<1>(); }
        else            { cp_wait<0>(); }
        __syncthreads();
        const float* As = fcbuf + s * STG;
        const float* Bs = As + BM * LDA;
        #pragma unroll
        for (int kk = 0; kk < BK; kk += 8) {
            wmma::fragment<wmma::matrix_a, 16, 16, 8, wmma::precision::tf32, wmma::row_major> a0, a1;
            wmma::fragment<wmma::matrix_b, 16, 16, 8, wmma::precision::tf32, wmma::row_major> b0, b1;
            wmma::load_matrix_sync(a0, As + (wm * 32) * LDA + kk, LDA);
            wmma::load_matrix_sync(a1, As + (wm * 32 + 16) * LDA + kk, LDA);
            wmma::load_matrix_sync(b0, Bs + kk * LDB + wn * 32, LDB);
            wmma::load_matrix_sync(b1, Bs + kk * LDB + wn * 32 + 16, LDB);
            wmma::mma_sync(acc[0][0], a0, b0, acc[0][0]);
            wmma::mma_sync(acc[0][1], a0, b1, acc[0][1]);
            wmma::mma_sync(acc[1][0], a1, b0, acc[1][0]);
            wmma::mma_sync(acc[1][1], a1, b1, acc[1][1]);
        }
        __syncthreads();
    }

    float* Cs = fcbuf;                          // 128 x 68
    #pragma unroll
    for (int i = 0; i < 2; i++)
        #pragma unroll
        for (int j = 0; j < 2; j++)
            wmma::store_matrix_sync(Cs + (wm * 32 + i * 16) * LDB + wn * 32 + j * 16,
                                    acc[i][j], LDB, wmma::mem_row_major);
    __syncthreads();
    #pragma unroll
    for (int t = 0; t < 32; t++) {               // 128*64/256
        int i = tid + t * 256;
        int r = i >> 6, c = i & 63;
        int gr = m0 + r, gc = n0 + c;
        if (gr < N_DIM && gc < F_CNN) {
            float v = Cs[r * LDB + c] + bfc[gc];
            g_feat[(size_t)gr * F_CNN + gc] = v > 0.f ? v : 0.f;
        }
    }
}

// ---------------- pairs: outer product write (HBM-bound) + labels ------------
#define NF2 621   // 1242/2

__global__ void k_pairs(float* __restrict__ out, const float* __restrict__ rel,
                        size_t labels_off) {
    __shared__ float2 srna[NF2];
    int i = blockIdx.x;                 // 0..599
    int tid = threadIdx.x;              // 640
    const float2* rrow = (const float2*)(g_feat + (size_t)i * F_CNN);
    if (tid < NF2) srna[tid] = rrow[tid];
    __syncthreads();

    if (blockIdx.y == 0 && tid >= NF2 && tid < NF2 + 16) {
        int l = tid - NF2;
        for (int j = l; j < D_DIM; j += 16)
            out[labels_off + (size_t)i * D_DIM + j] = rel[(size_t)i * D_DIM + j];
    }
    if (tid >= NF2) return;
    float2 rv = srna[tid];
    int j0 = blockIdx.y * 48;
    #pragma unroll 2
    for (int j = j0; j < j0 + 48; j++) {
        const float2* drow = (const float2*)(g_feat + (size_t)(R_DIM + j) * F_CNN);
        float2 dv = drow[tid];
        float2 o; o.x = rv.x * dv.x; o.y = rv.y * dv.y;
        __stcs((float2*)(out + (size_t)(i * D_DIM + j) * F_CNN) + tid, o);
    }
}

// ---------------- launch ------------------------------------------------------
extern "C" void kernel_launch(void* const* d_in, const int* in_sizes, int n_in,
                              void* d_out, int out_size) {
    const int*   ei   = (const int*)d_in[0];
    const float* met  = (const float*)d_in[1];
    const float* dis  = (const float*)d_in[2];
    const float* rel  = (const float*)d_in[3];
    const float* Wr   = (const float*)d_in[4];
    const float* Wd   = (const float*)d_in[5];
    const float* Wl   = (const float*)d_in[6];
    const float* bl   = (const float*)d_in[7];
    const float* Wrt  = (const float*)d_in[8];
    const float* br   = (const float*)d_in[9];
    const float* att  = (const float*)d_in[10];
    const float* gb   = (const float*)d_in[11];
    const float* c1w  = (const float*)d_in[12];
    const float* c1b  = (const float*)d_in[13];
    const float* c4w  = (const float*)d_in[14];
    const float* c4b  = (const float*)d_in[15];
    const float* c16w = (const float*)d_in[16];
    const float* c16b = (const float*)d_in[17];
    const float* c32w = (const float*)d_in[18];
    const float* c32b = (const float*)d_in[19];
    const float* Wfc  = (const float*)d_in[20];
    const float* bfc  = (const float*)d_in[21];
    float* out = (float*)d_out;

    static int smem_set = 0;
    if (!smem_set) {
        cudaFuncSetAttribute(k_fc, cudaFuncAttributeMaxDynamicSharedMemorySize, FC_SMEM);
        smem_set = 1;
    }

    int pad_total = KP * NP + (MP - N_DIM) * NP;
    k_pad<<<(pad_total + 255) / 256, 256>>>(Wfc);
    k_prep<<<1, 1024>>>(ei);
    k_hx<<<105, 512>>>(met, dis, Wr, Wd, Wl, bl, Wrt, br);
    k_logits<<<(ME * 32 + 255) / 256, 256>>>(ei, att);
    k_gatconv<<<N_DIM, 256>>>(ei, gb, c1w, c1b, c4w, c4b, c16w, c16b, c32w, c32b);
    k_fc<<<dim3(NP / BN, MP / BM), 256, FC_SMEM>>>(bfc);
    size_t labels_off = (size_t)out_size - (size_t)R_DIM * D_DIM;
    k_pairs<<<dim3(R_DIM, 5), 640>>>(out, rel, labels_off);
}